// round 6
// baseline (speedup 1.0000x reference)
#include <cuda_runtime.h>
#include <math.h>

// ---------------------------------------------------------------------------
// ProteinEmbeddingPooling — restructured:
//   q0  = emb[:,0,:] @ Wq^T + bq ; kq = q0 @ Wk ; cb = q0 . bk
//   scores[b,s] = scale*(emb[b,s].kq[b] + cb[b])  (mask)
//   pooled[b]   = softmax_s(scores) . emb[b,:,:]   (tiled online softmax)
//   ctx = pooled @ Wv^T + bv ; h = ctx @ Wo^T + bo ; LN ; ReLU
// ---------------------------------------------------------------------------

#define BB 32
#define SS 1024
#define DD 1280
#define CTAS_PER_B 16
#define WPB 4
#define NCP CTAS_PER_B                   // combined partials per batch
#define RPW (SS / (CTAS_PER_B * WPB))    // 16 rows per warp
#define TT 8                             // rows per softmax tile

// ---- scratch (device globals; no allocation allowed) ----
__device__ float g_q0[BB * DD];
__device__ float g_kq[BB * DD];
__device__ float g_pm[BB * NCP];
__device__ float g_pl[BB * NCP];
__device__ float g_pacc[(size_t)BB * NCP * DD];   // 2.6 MB
__device__ float g_pooled[BB * DD];
__device__ float g_ctx[BB * DD];
__device__ float g_h[BB * DD];

// ---------------------------------------------------------------------------
__global__ void init_kernel(const float* __restrict__ bq,
                            const float* __restrict__ bv,
                            const float* __restrict__ bo)
{
    int i = blockIdx.x * blockDim.x + threadIdx.x;
    if (i < BB * DD) {
        int n = i % DD;
        g_q0[i]  = bq[n];
        g_kq[i]  = 0.0f;
        g_ctx[i] = bv[n];
        g_h[i]   = bo[n];
    }
}

// ---------------------------------------------------------------------------
// small GEMM: C[32,1280] += A[32,1280] * op(W)   (see R4 — unchanged)
// ---------------------------------------------------------------------------
template<int MODE, int SRC, int DST>
__global__ void __launch_bounds__(256) gemm32(const float* __restrict__ Aext,
                                              size_t lda,
                                              const float* __restrict__ W)
{
    constexpr int NT = 64;
    constexpr int KC = 40;

    const float* A = (SRC == 0) ? Aext
                   : (SRC == 1) ? g_q0
                   : (SRC == 2) ? g_pooled
                   :              g_ctx;
    if (SRC != 0) lda = DD;
    float* C = (DST == 0) ? g_q0
             : (DST == 1) ? g_kq
             : (DST == 2) ? g_ctx
             :              g_h;

    __shared__ float As[KC][33];     // [k][m]
    __shared__ float Ws[KC][68];     // [k][n]

    const int tid = threadIdx.x;
    const int n0 = blockIdx.x * NT;
    const int k0 = blockIdx.y * KC;
    const int k04 = k0 >> 2;

    const float4* A4 = reinterpret_cast<const float4*>(A);
    const size_t lda4 = lda >> 2;
#pragma unroll
    for (int i = 0; i < 2; i++) {
        int f = tid + i * 256;
        if (f < 320) {
            int m = f / 10, kc4 = f % 10;
            float4 v = A4[(size_t)m * lda4 + k04 + kc4];
            As[kc4 * 4 + 0][m] = v.x;
            As[kc4 * 4 + 1][m] = v.y;
            As[kc4 * 4 + 2][m] = v.z;
            As[kc4 * 4 + 3][m] = v.w;
        }
    }

    const float4* W4 = reinterpret_cast<const float4*>(W);
    if (MODE == 1) {
#pragma unroll
        for (int i = 0; i < 3; i++) {
            int f = tid + i * 256;
            if (f < 640) {
                int kr = f >> 4, nc = f & 15;
                float4 v = W4[(size_t)(k0 + kr) * (DD / 4) + (n0 >> 2) + nc];
                reinterpret_cast<float4*>(&Ws[kr][0])[nc] = v;
            }
        }
    } else {
#pragma unroll
        for (int i = 0; i < 3; i++) {
            int f = tid + i * 256;
            if (f < 640) {
                int n = f / 10, kc4 = f % 10;
                float4 v = W4[(size_t)(n0 + n) * (DD / 4) + k04 + kc4];
                Ws[kc4 * 4 + 0][n] = v.x;
                Ws[kc4 * 4 + 1][n] = v.y;
                Ws[kc4 * 4 + 2][n] = v.z;
                Ws[kc4 * 4 + 3][n] = v.w;
            }
        }
    }
    __syncthreads();

    const int tx = tid & 15;
    const int ty = tid >> 4;

    float acc0[4] = {}, acc1[4] = {};
#pragma unroll 8
    for (int k = 0; k < KC; k++) {
        const float a0 = As[k][ty];
        const float a1 = As[k][ty + 16];
        const float4 w = reinterpret_cast<const float4*>(&Ws[k][0])[tx];
        acc0[0] = fmaf(a0, w.x, acc0[0]);
        acc0[1] = fmaf(a0, w.y, acc0[1]);
        acc0[2] = fmaf(a0, w.z, acc0[2]);
        acc0[3] = fmaf(a0, w.w, acc0[3]);
        acc1[0] = fmaf(a1, w.x, acc1[0]);
        acc1[1] = fmaf(a1, w.y, acc1[1]);
        acc1[2] = fmaf(a1, w.z, acc1[2]);
        acc1[3] = fmaf(a1, w.w, acc1[3]);
    }

    float* c0 = &C[(size_t)ty * DD + n0 + tx * 4];
    float* c1 = &C[(size_t)(ty + 16) * DD + n0 + tx * 4];
#pragma unroll
    for (int j = 0; j < 4; j++) atomicAdd(c0 + j, acc0[j]);
#pragma unroll
    for (int j = 0; j < 4; j++) atomicAdd(c1 + j, acc1[j]);
}

// ---------------------------------------------------------------------------
// attention + pooling, TILED online softmax (T=8 rows per step):
//   phase A: 8 independent dot products (x transient -> low reg pressure)
//   phase B: re-read same 8 rows (L2-hot) and accumulate with known weights
// grid 512 (32 b x 16 CTAs), block 128 (4 warps x 16 rows). kq in registers.
// ---------------------------------------------------------------------------
__global__ void __launch_bounds__(128, 3) attn_kernel(
    const float* __restrict__ emb,
    const int* __restrict__ mask,
    const float* __restrict__ bk,
    float scale)
{
    __shared__ float4 sacc[WPB][DD / 4];
    __shared__ float sm[WPB], sl[WPB], scb;

    const int b = blockIdx.x / CTAS_PER_B;
    const int cta = blockIdx.x % CTAS_PER_B;
    const int tid = threadIdx.x;
    const int warp = tid >> 5;
    const int lane = tid & 31;
    const int s0 = (cta * WPB + warp) * RPW;

    // kq -> registers (L2-hot broadcast across warps of this batch)
    const float4* kq4 = reinterpret_cast<const float4*>(g_kq + b * DD);
    float4 kq[10];
#pragma unroll
    for (int c = 0; c < 10; c++) kq[c] = __ldg(&kq4[c * 32 + lane]);

    // cb = q0[b].bk by warp 0
    if (warp == 0) {
        const float4* q04 = reinterpret_cast<const float4*>(g_q0 + b * DD);
        const float4* bk4 = reinterpret_cast<const float4*>(bk);
        float p = 0.0f;
#pragma unroll
        for (int c = 0; c < 10; c++) {
            const float4 q = __ldg(&q04[c * 32 + lane]);
            const float4 k = __ldg(&bk4[c * 32 + lane]);
            p = fmaf(q.x, k.x, p); p = fmaf(q.y, k.y, p);
            p = fmaf(q.z, k.z, p); p = fmaf(q.w, k.w, p);
        }
#pragma unroll
        for (int off = 16; off > 0; off >>= 1)
            p += __shfl_xor_sync(0xffffffffu, p, off);
        if (lane == 0) scb = p;
    }
    __syncthreads();
    const float cb = scb;

    const float* base = emb + (size_t)b * SS * DD;
    const int* mrow = mask + b * SS;

    float m = -INFINITY, l = 0.0f;
    float4 acc[10];
#pragma unroll
    for (int c = 0; c < 10; c++) acc[c] = make_float4(0.f, 0.f, 0.f, 0.f);

    for (int t = 0; t < RPW / TT; t++) {
        const int sBase = s0 + t * TT;

        // ---- phase A: 8 dot products, x transient ----
        float p[TT];
#pragma unroll
        for (int r = 0; r < TT; r++) {
            const float4* row =
                reinterpret_cast<const float4*>(base + (size_t)(sBase + r) * DD);
            float pa = 0.0f, pb = 0.0f;
#pragma unroll
            for (int c = 0; c < 10; c += 2) {
                const float4 xa = __ldg(&row[c * 32 + lane]);
                const float4 xb = __ldg(&row[(c + 1) * 32 + lane]);
                pa = fmaf(xa.x, kq[c].x, pa);
                pa = fmaf(xa.y, kq[c].y, pa);
                pa = fmaf(xa.z, kq[c].z, pa);
                pa = fmaf(xa.w, kq[c].w, pa);
                pb = fmaf(xb.x, kq[c + 1].x, pb);
                pb = fmaf(xb.y, kq[c + 1].y, pb);
                pb = fmaf(xb.z, kq[c + 1].z, pb);
                pb = fmaf(xb.w, kq[c + 1].w, pb);
            }
            p[r] = pa + pb;
        }

        // ---- warp reduce all 8 (independent chains pipeline) ----
#pragma unroll
        for (int off = 16; off > 0; off >>= 1)
#pragma unroll
            for (int r = 0; r < TT; r++)
                p[r] += __shfl_xor_sync(0xffffffffu, p[r], off);

        // ---- tile softmax update ----
        float Mt = -INFINITY;
#pragma unroll
        for (int r = 0; r < TT; r++) {
            float sc = (p[r] + cb) * scale;
            if (mrow[sBase + r] == 0) sc = -1e9f;
            p[r] = sc;
            Mt = fmaxf(Mt, sc);
        }
        const float mn = fmaxf(m, Mt);
        const float fac = __expf(m - mn);   // first tile: exp(-inf) = 0
        l *= fac;
#pragma unroll
        for (int c = 0; c < 10; c++) {
            acc[c].x *= fac; acc[c].y *= fac;
            acc[c].z *= fac; acc[c].w *= fac;
        }
        m = mn;
#pragma unroll
        for (int r = 0; r < TT; r++) {
            p[r] = __expf(p[r] - m);
            l += p[r];
        }

        // ---- phase B: re-read rows (L2-hot), accumulate ----
#pragma unroll
        for (int r = 0; r < TT; r++) {
            const float4* row =
                reinterpret_cast<const float4*>(base + (size_t)(sBase + r) * DD);
            const float wr = p[r];
#pragma unroll
            for (int c = 0; c < 10; c++) {
                const float4 x = __ldcs(&row[c * 32 + lane]);
                acc[c].x = fmaf(wr, x.x, acc[c].x);
                acc[c].y = fmaf(wr, x.y, acc[c].y);
                acc[c].z = fmaf(wr, x.z, acc[c].z);
                acc[c].w = fmaf(wr, x.w, acc[c].w);
            }
        }
    }

    // ---- CTA-level merge of 4 warp partials -> 1 partial ----
#pragma unroll
    for (int c = 0; c < 10; c++) sacc[warp][c * 32 + lane] = acc[c];
    if (lane == 0) { sm[warp] = m; sl[warp] = l; }
    __syncthreads();

    const float M = fmaxf(fmaxf(sm[0], sm[1]), fmaxf(sm[2], sm[3]));
    const float f0 = __expf(sm[0] - M), f1 = __expf(sm[1] - M);
    const float f2 = __expf(sm[2] - M), f3 = __expf(sm[3] - M);
    const float L = f0 * sl[0] + f1 * sl[1] + f2 * sl[2] + f3 * sl[3];

    const int pidx = b * NCP + cta;
    float4* pa4 = reinterpret_cast<float4*>(g_pacc + (size_t)pidx * DD);
#pragma unroll
    for (int i = 0; i < 3; i++) {
        const int idx = tid + i * 128;
        if (idx < DD / 4) {
            const float4 a0 = sacc[0][idx], a1 = sacc[1][idx];
            const float4 a2 = sacc[2][idx], a3 = sacc[3][idx];
            float4 s;
            s.x = fmaf(f0, a0.x, fmaf(f1, a1.x, fmaf(f2, a2.x, f3 * a3.x)));
            s.y = fmaf(f0, a0.y, fmaf(f1, a1.y, fmaf(f2, a2.y, f3 * a3.y)));
            s.z = fmaf(f0, a0.z, fmaf(f1, a1.z, fmaf(f2, a2.z, f3 * a3.z)));
            s.w = fmaf(f0, a0.w, fmaf(f1, a1.w, fmaf(f2, a2.w, f3 * a3.w)));
            pa4[idx] = s;
        }
    }
    if (tid == 0) { g_pm[pidx] = M; g_pl[pidx] = L; }
}

// ---------------------------------------------------------------------------
// combine 16 CTA-partials -> pooled[b,:]. grid 32, block 320.
// ---------------------------------------------------------------------------
__global__ void __launch_bounds__(320) combine_kernel()
{
    const int b = blockIdx.x;
    __shared__ float fs[NCP], ls[NCP];

    if (threadIdx.x < NCP) {
        float M = -INFINITY;
#pragma unroll
        for (int p = 0; p < NCP; p++) M = fmaxf(M, g_pm[b * NCP + p]);
        const float f = __expf(g_pm[b * NCP + threadIdx.x] - M);
        fs[threadIdx.x] = f;
        ls[threadIdx.x] = f * g_pl[b * NCP + threadIdx.x];
    }
    __syncthreads();

    float L = 0.0f;
#pragma unroll
    for (int p = 0; p < NCP; p++) L += ls[p];
    const float invL = 1.0f / L;

    const int d4 = threadIdx.x;   // 0..319
    float4 sum = make_float4(0.f, 0.f, 0.f, 0.f);
#pragma unroll
    for (int p = 0; p < NCP; p++) {
        const float f = fs[p];
        const float4 a = reinterpret_cast<const float4*>(
            g_pacc + (size_t)(b * NCP + p) * DD)[d4];
        sum.x = fmaf(f, a.x, sum.x);
        sum.y = fmaf(f, a.y, sum.y);
        sum.z = fmaf(f, a.z, sum.z);
        sum.w = fmaf(f, a.w, sum.w);
    }
    reinterpret_cast<float4*>(g_pooled + b * DD)[d4] =
        make_float4(sum.x * invL, sum.y * invL, sum.z * invL, sum.w * invL);
}

// ---------------------------------------------------------------------------
// LayerNorm + ReLU on h[32,1280] -> out. grid 32, block 256.
// ---------------------------------------------------------------------------
__global__ void __launch_bounds__(256) ln_kernel(const float* __restrict__ gamma,
                                                 const float* __restrict__ beta,
                                                 float* __restrict__ out)
{
    const int b = blockIdx.x, tid = threadIdx.x;
    float x[5];
    float s = 0.0f, s2 = 0.0f;
#pragma unroll
    for (int i = 0; i < 5; i++) {
        x[i] = g_h[b * DD + tid + i * 256];
        s += x[i];
        s2 = fmaf(x[i], x[i], s2);
    }
    __shared__ float rs[256], rs2[256];
    rs[tid] = s; rs2[tid] = s2;
    __syncthreads();
    for (int off = 128; off > 0; off >>= 1) {
        if (tid < off) { rs[tid] += rs[tid + off]; rs2[tid] += rs2[tid + off]; }
        __syncthreads();
    }
    const float mu  = rs[0] * (1.0f / DD);
    float var = rs2[0] * (1.0f / DD) - mu * mu;
    var = fmaxf(var, 0.0f);
    const float inv = rsqrtf(var + 1e-5f);
#pragma unroll
    for (int i = 0; i < 5; i++) {
        const int n = tid + i * 256;
        const float v = (x[i] - mu) * inv * gamma[n] + beta[n];
        out[b * DD + n] = fmaxf(v, 0.0f);
    }
}

// ---------------------------------------------------------------------------
extern "C" void kernel_launch(void* const* d_in, const int* in_sizes, int n_in,
                              void* d_out, int out_size)
{
    (void)in_sizes; (void)n_in; (void)out_size;

    const float* emb   = (const float*)d_in[0];
    const int*   mask  = (const int*)d_in[1];
    const float* Wq    = (const float*)d_in[2];
    const float* bq    = (const float*)d_in[3];
    const float* Wk    = (const float*)d_in[4];
    const float* bk    = (const float*)d_in[5];
    const float* Wv    = (const float*)d_in[6];
    const float* bv    = (const float*)d_in[7];
    const float* Wo    = (const float*)d_in[8];
    const float* bo    = (const float*)d_in[9];
    const float* gamma = (const float*)d_in[10];
    const float* beta  = (const float*)d_in[11];
    float* out = (float*)d_out;

    const float scale = 1.0f / sqrtf((float)DD);
    const dim3 ggrid(DD / 64, 32);   // 20 n-tiles x 32 k-splits = 640 CTAs

    init_kernel<<<(BB * DD + 255) / 256, 256>>>(bq, bv, bo);
    gemm32<0, 0, 0><<<ggrid, 256>>>(emb, (size_t)SS * DD, Wq);     // q0
    gemm32<1, 1, 1><<<ggrid, 256>>>(nullptr, 0, Wk);               // kq = q0@Wk
    attn_kernel<<<BB * CTAS_PER_B, 128>>>(emb, mask, bk, scale);   // pool
    combine_kernel<<<BB, 320>>>();
    gemm32<0, 2, 2><<<ggrid, 256>>>(nullptr, 0, Wv);               // ctx
    gemm32<0, 3, 3><<<ggrid, 256>>>(nullptr, 0, Wo);               // h
    ln_kernel<<<BB, 256>>>(gamma, beta, out);
}

// round 7
// speedup vs baseline: 1.1057x; 1.1057x over previous
#include <cuda_runtime.h>
#include <math.h>

// ---------------------------------------------------------------------------
// ProteinEmbeddingPooling — restructured:
//   q0  = emb[:,0,:] @ Wq^T + bq ; kq = q0 @ Wk ; cb = q0 . bk
//   scores[b,s] = scale*(emb[b,s].kq[b] + cb[b])  (mask)
//   pooled[b]   = softmax_s(scores) . emb[b,:,:]   (block-wide online softmax)
//   ctx = pooled @ Wv^T + bv ; h = ctx @ Wo^T + bo ; LN ; ReLU
// ---------------------------------------------------------------------------

#define BB 32
#define SS 1024
#define DD 1280
#define ANC 32                    // attn CTAs per batch
#define AROWS (SS / ANC)          // 32 rows per CTA
#define ATT 4                     // rows per tile
#define NCP ANC                   // partials per batch

// ---- scratch (device globals; no allocation allowed) ----
__device__ float g_q0[BB * DD];
__device__ float g_kq[BB * DD];
__device__ float g_pm[BB * NCP];
__device__ float g_pl[BB * NCP];
__device__ float g_pacc[(size_t)BB * NCP * DD];   // 5.24 MB
__device__ float g_pooled[BB * DD];
__device__ float g_ctx[BB * DD];
__device__ float g_h[BB * DD];

// ---------------------------------------------------------------------------
__global__ void init_kernel(const float* __restrict__ bq,
                            const float* __restrict__ bv,
                            const float* __restrict__ bo)
{
    int i = blockIdx.x * blockDim.x + threadIdx.x;
    if (i < BB * DD) {
        int n = i % DD;
        g_q0[i]  = bq[n];
        g_kq[i]  = 0.0f;
        g_ctx[i] = bv[n];
        g_h[i]   = bo[n];
    }
}

// ---------------------------------------------------------------------------
// small GEMM: C[32,1280] += A[32,1280] * op(W)   (unchanged from R4)
// ---------------------------------------------------------------------------
template<int MODE, int SRC, int DST>
__global__ void __launch_bounds__(256) gemm32(const float* __restrict__ Aext,
                                              size_t lda,
                                              const float* __restrict__ W)
{
    constexpr int NT = 64;
    constexpr int KC = 40;

    const float* A = (SRC == 0) ? Aext
                   : (SRC == 1) ? g_q0
                   : (SRC == 2) ? g_pooled
                   :              g_ctx;
    if (SRC != 0) lda = DD;
    float* C = (DST == 0) ? g_q0
             : (DST == 1) ? g_kq
             : (DST == 2) ? g_ctx
             :              g_h;

    __shared__ float As[KC][33];     // [k][m]
    __shared__ float Ws[KC][68];     // [k][n]

    const int tid = threadIdx.x;
    const int n0 = blockIdx.x * NT;
    const int k0 = blockIdx.y * KC;
    const int k04 = k0 >> 2;

    const float4* A4 = reinterpret_cast<const float4*>(A);
    const size_t lda4 = lda >> 2;
#pragma unroll
    for (int i = 0; i < 2; i++) {
        int f = tid + i * 256;
        if (f < 320) {
            int m = f / 10, kc4 = f % 10;
            float4 v = A4[(size_t)m * lda4 + k04 + kc4];
            As[kc4 * 4 + 0][m] = v.x;
            As[kc4 * 4 + 1][m] = v.y;
            As[kc4 * 4 + 2][m] = v.z;
            As[kc4 * 4 + 3][m] = v.w;
        }
    }

    const float4* W4 = reinterpret_cast<const float4*>(W);
    if (MODE == 1) {
#pragma unroll
        for (int i = 0; i < 3; i++) {
            int f = tid + i * 256;
            if (f < 640) {
                int kr = f >> 4, nc = f & 15;
                float4 v = W4[(size_t)(k0 + kr) * (DD / 4) + (n0 >> 2) + nc];
                reinterpret_cast<float4*>(&Ws[kr][0])[nc] = v;
            }
        }
    } else {
#pragma unroll
        for (int i = 0; i < 3; i++) {
            int f = tid + i * 256;
            if (f < 640) {
                int n = f / 10, kc4 = f % 10;
                float4 v = W4[(size_t)(n0 + n) * (DD / 4) + k04 + kc4];
                Ws[kc4 * 4 + 0][n] = v.x;
                Ws[kc4 * 4 + 1][n] = v.y;
                Ws[kc4 * 4 + 2][n] = v.z;
                Ws[kc4 * 4 + 3][n] = v.w;
            }
        }
    }
    __syncthreads();

    const int tx = tid & 15;
    const int ty = tid >> 4;

    float acc0[4] = {}, acc1[4] = {};
#pragma unroll 8
    for (int k = 0; k < KC; k++) {
        const float a0 = As[k][ty];
        const float a1 = As[k][ty + 16];
        const float4 w = reinterpret_cast<const float4*>(&Ws[k][0])[tx];
        acc0[0] = fmaf(a0, w.x, acc0[0]);
        acc0[1] = fmaf(a0, w.y, acc0[1]);
        acc0[2] = fmaf(a0, w.z, acc0[2]);
        acc0[3] = fmaf(a0, w.w, acc0[3]);
        acc1[0] = fmaf(a1, w.x, acc1[0]);
        acc1[1] = fmaf(a1, w.y, acc1[1]);
        acc1[2] = fmaf(a1, w.z, acc1[2]);
        acc1[3] = fmaf(a1, w.w, acc1[3]);
    }

    float* c0 = &C[(size_t)ty * DD + n0 + tx * 4];
    float* c1 = &C[(size_t)(ty + 16) * DD + n0 + tx * 4];
#pragma unroll
    for (int j = 0; j < 4; j++) atomicAdd(c0 + j, acc0[j]);
#pragma unroll
    for (int j = 0; j < 4; j++) atomicAdd(c1 + j, acc1[j]);
}

// ---------------------------------------------------------------------------
// attention + pooling: block-wide row processing.
// block = 320 threads, one float4 per thread = one full 1280-float row.
// grid 1024 (32 b x 32 CTAs), 32 rows per CTA, tiles of 4 rows.
// Per-thread state tiny (~64 regs). Scores via 2-level block reduction.
// All threads share m/l -> partial written directly, no merge step.
// ---------------------------------------------------------------------------
__global__ void __launch_bounds__(320) attn_kernel(
    const float* __restrict__ emb,
    const int* __restrict__ mask,
    const float* __restrict__ bk,
    float scale)
{
    __shared__ float sred[ATT][12];     // [row][warp], padded
    __shared__ float sscore[ATT];
    __shared__ float scb;
    __shared__ int   smask[AROWS];

    const int b    = blockIdx.x / ANC;
    const int cta  = blockIdx.x % ANC;
    const int tid  = threadIdx.x;       // 0..319
    const int warp = tid >> 5;          // 0..9
    const int lane = tid & 31;
    const int s0   = cta * AROWS;

    // mask slice -> smem (warp 1; AROWS == 32)
    if (warp == 1) smask[lane] = mask[b * SS + s0 + lane];

    // kq -> one float4 per thread
    const float4 kq =
        __ldg(&reinterpret_cast<const float4*>(g_kq + b * DD)[tid]);

    // cb = q0[b] . bk by warp 0
    if (warp == 0) {
        const float4* q04 = reinterpret_cast<const float4*>(g_q0 + b * DD);
        const float4* bk4 = reinterpret_cast<const float4*>(bk);
        float p = 0.0f;
#pragma unroll
        for (int c = 0; c < 10; c++) {
            const float4 q = __ldg(&q04[c * 32 + lane]);
            const float4 k = __ldg(&bk4[c * 32 + lane]);
            p = fmaf(q.x, k.x, p); p = fmaf(q.y, k.y, p);
            p = fmaf(q.z, k.z, p); p = fmaf(q.w, k.w, p);
        }
#pragma unroll
        for (int off = 16; off > 0; off >>= 1)
            p += __shfl_xor_sync(0xffffffffu, p, off);
        if (lane == 0) scb = p;
    }

    const float4* base4 =
        reinterpret_cast<const float4*>(emb + (size_t)b * SS * DD);

    // preload first tile (independent of the sync above)
    float4 x[ATT];
#pragma unroll
    for (int r = 0; r < ATT; r++)
        x[r] = __ldcs(&base4[(size_t)(s0 + r) * (DD / 4) + tid]);

    __syncthreads();
    const float cb = scb;

    float m = -INFINITY, l = 0.0f;
    float4 acc = make_float4(0.f, 0.f, 0.f, 0.f);

    constexpr int NTILES = AROWS / ATT;   // 8
#pragma unroll
    for (int t = 0; t < NTILES; t++) {
        const int sb = t * ATT;

        // ---- per-thread partial dots, warp reduce (4 independent chains) ----
        float p[ATT];
#pragma unroll
        for (int r = 0; r < ATT; r++) {
            p[r] = x[r].x * kq.x;
            p[r] = fmaf(x[r].y, kq.y, p[r]);
            p[r] = fmaf(x[r].z, kq.z, p[r]);
            p[r] = fmaf(x[r].w, kq.w, p[r]);
        }
#pragma unroll
        for (int off = 16; off > 0; off >>= 1)
#pragma unroll
            for (int r = 0; r < ATT; r++)
                p[r] += __shfl_xor_sync(0xffffffffu, p[r], off);
        if (lane == 0) {
#pragma unroll
            for (int r = 0; r < ATT; r++) sred[r][warp] = p[r];
        }
        __syncthreads();

        // ---- prefetch next tile (overlaps score computation) ----
        float4 y[ATT];
        if (t + 1 < NTILES) {
#pragma unroll
            for (int r = 0; r < ATT; r++)
                y[r] = __ldcs(
                    &base4[(size_t)(s0 + sb + ATT + r) * (DD / 4) + tid]);
        }

        // ---- warp 0 finalizes the 4 scores ----
        if (warp == 0 && lane < ATT) {
            float s = 0.0f;
#pragma unroll
            for (int w = 0; w < 10; w++) s += sred[lane][w];
            float sc = (s + cb) * scale;
            if (smask[sb + lane] == 0) sc = -1e9f;
            sscore[lane] = sc;
        }
        __syncthreads();

        // ---- online softmax update (identical across block) ----
        float sc[ATT];
#pragma unroll
        for (int r = 0; r < ATT; r++) sc[r] = sscore[r];
        float Mt = fmaxf(fmaxf(sc[0], sc[1]), fmaxf(sc[2], sc[3]));
        const float mn = fmaxf(m, Mt);
        const float fac = __expf(m - mn);   // first tile: exp(-inf)=0
        l *= fac;
        acc.x *= fac; acc.y *= fac; acc.z *= fac; acc.w *= fac;
        m = mn;
#pragma unroll
        for (int r = 0; r < ATT; r++) {
            const float w = __expf(sc[r] - m);
            l += w;
            acc.x = fmaf(w, x[r].x, acc.x);
            acc.y = fmaf(w, x[r].y, acc.y);
            acc.z = fmaf(w, x[r].z, acc.z);
            acc.w = fmaf(w, x[r].w, acc.w);
        }
        if (t + 1 < NTILES) {
#pragma unroll
            for (int r = 0; r < ATT; r++) x[r] = y[r];
        }
    }

    // ---- write partial directly (m/l identical across block) ----
    const int pidx = b * NCP + cta;
    reinterpret_cast<float4*>(g_pacc + (size_t)pidx * DD)[tid] = acc;
    if (tid == 0) { g_pm[pidx] = m; g_pl[pidx] = l; }
}

// ---------------------------------------------------------------------------
// combine 32 CTA-partials -> pooled[b,:]. grid 32, block 320.
// ---------------------------------------------------------------------------
__global__ void __launch_bounds__(320) combine_kernel()
{
    const int b = blockIdx.x;
    __shared__ float fs[NCP], ls[NCP];

    if (threadIdx.x < NCP) {
        float M = -INFINITY;
#pragma unroll
        for (int p = 0; p < NCP; p++) M = fmaxf(M, g_pm[b * NCP + p]);
        const float f = __expf(g_pm[b * NCP + threadIdx.x] - M);
        fs[threadIdx.x] = f;
        ls[threadIdx.x] = f * g_pl[b * NCP + threadIdx.x];
    }
    __syncthreads();

    float L = 0.0f;
#pragma unroll
    for (int p = 0; p < NCP; p++) L += ls[p];
    const float invL = 1.0f / L;

    const int d4 = threadIdx.x;   // 0..319
    float4 sum = make_float4(0.f, 0.f, 0.f, 0.f);
#pragma unroll 8
    for (int p = 0; p < NCP; p++) {
        const float f = fs[p];
        const float4 a = reinterpret_cast<const float4*>(
            g_pacc + (size_t)(b * NCP + p) * DD)[d4];
        sum.x = fmaf(f, a.x, sum.x);
        sum.y = fmaf(f, a.y, sum.y);
        sum.z = fmaf(f, a.z, sum.z);
        sum.w = fmaf(f, a.w, sum.w);
    }
    reinterpret_cast<float4*>(g_pooled + b * DD)[d4] =
        make_float4(sum.x * invL, sum.y * invL, sum.z * invL, sum.w * invL);
}

// ---------------------------------------------------------------------------
// LayerNorm + ReLU on h[32,1280] -> out. grid 32, block 256.
// ---------------------------------------------------------------------------
__global__ void __launch_bounds__(256) ln_kernel(const float* __restrict__ gamma,
                                                 const float* __restrict__ beta,
                                                 float* __restrict__ out)
{
    const int b = blockIdx.x, tid = threadIdx.x;
    float x[5];
    float s = 0.0f, s2 = 0.0f;
#pragma unroll
    for (int i = 0; i < 5; i++) {
        x[i] = g_h[b * DD + tid + i * 256];
        s += x[i];
        s2 = fmaf(x[i], x[i], s2);
    }
    __shared__ float rs[256], rs2[256];
    rs[tid] = s; rs2[tid] = s2;
    __syncthreads();
    for (int off = 128; off > 0; off >>= 1) {
        if (tid < off) { rs[tid] += rs[tid + off]; rs2[tid] += rs2[tid + off]; }
        __syncthreads();
    }
    const float mu  = rs[0] * (1.0f / DD);
    float var = rs2[0] * (1.0f / DD) - mu * mu;
    var = fmaxf(var, 0.0f);
    const float inv = rsqrtf(var + 1e-5f);
#pragma unroll
    for (int i = 0; i < 5; i++) {
        const int n = tid + i * 256;
        const float v = (x[i] - mu) * inv * gamma[n] + beta[n];
        out[b * DD + n] = fmaxf(v, 0.0f);
    }
}

// ---------------------------------------------------------------------------
extern "C" void kernel_launch(void* const* d_in, const int* in_sizes, int n_in,
                              void* d_out, int out_size)
{
    (void)in_sizes; (void)n_in; (void)out_size;

    const float* emb   = (const float*)d_in[0];
    const int*   mask  = (const int*)d_in[1];
    const float* Wq    = (const float*)d_in[2];
    const float* bq    = (const float*)d_in[3];
    const float* Wk    = (const float*)d_in[4];
    const float* bk    = (const float*)d_in[5];
    const float* Wv    = (const float*)d_in[6];
    const float* bv    = (const float*)d_in[7];
    const float* Wo    = (const float*)d_in[8];
    const float* bo    = (const float*)d_in[9];
    const float* gamma = (const float*)d_in[10];
    const float* beta  = (const float*)d_in[11];
    float* out = (float*)d_out;

    const float scale = 1.0f / sqrtf((float)DD);
    const dim3 ggrid(DD / 64, 32);   // 20 n-tiles x 32 k-splits = 640 CTAs

    init_kernel<<<(BB * DD + 255) / 256, 256>>>(bq, bv, bo);
    gemm32<0, 0, 0><<<ggrid, 256>>>(emb, (size_t)SS * DD, Wq);     // q0
    gemm32<1, 1, 1><<<ggrid, 256>>>(nullptr, 0, Wk);               // kq = q0@Wk
    attn_kernel<<<BB * ANC, 320>>>(emb, mask, bk, scale);          // pool
    combine_kernel<<<BB, 320>>>();
    gemm32<0, 2, 2><<<ggrid, 256>>>(nullptr, 0, Wv);               // ctx
    gemm32<0, 3, 3><<<ggrid, 256>>>(nullptr, 0, Wo);               // h
    ln_kernel<<<BB, 256>>>(gamma, beta, out);
}